// round 6
// baseline (speedup 1.0000x reference)
#include <cuda_runtime.h>
#include <cuda_bf16.h>
#include <cstdint>

// LocallyConnected2d: out[b,o,y,x] = sum_{c,k} x[b,c,y+i,x+j] * w[o,c,y,x,k]
// B=16, C_IN=16, C_OUT=16, H=W=64, OH=OW=62, K=3x3.
//
// R6: 5 blocks/SM (occupancy 62.5% cap), x staged via LDG->reg->STS pipeline
// (no 4B LDGSTS), w staged via 16B cp.async into natural [o][144] layout.
// Triple-buffered, one barrier/channel, c-split 4 + atomicAdd into memset-0
// output (4 commutative contributions -> deterministic).

#define B_  16
#define CIN 16
#define CO  16
#define H_  64
#define W_  64
#define OH_ 62
#define OW_ 62
#define TX  16

#define NC  4                       // channels per block (4-way c split)
#define WROW 148                    // weight smem row stride (floats, 16B mult)
#define WBUF (CO * WROW)            // 2368 floats
#define XBUF (8 * 3 * 40)           // 960 floats: [bpair][row][20 cols x 2]

#define WOSTRIDE (CIN * OH_ * OW_ * 9)   // weight float stride per o: 553536
#define WCSTRIDE (OH_ * OW_ * 9)         // weight float stride per c: 34596
#define XCSTRIDE (H_ * W_)               // x float stride per c: 4096

__device__ __forceinline__ void ffma2(unsigned long long& d,
                                      unsigned long long a,
                                      unsigned long long b) {
    asm("fma.rn.f32x2 %0, %1, %2, %0;" : "+l"(d) : "l"(a), "l"(b));
}

__device__ __forceinline__ unsigned long long bcast2(float v) {
    unsigned long long p;
    asm("mov.b64 %0, {%1, %1};" : "=l"(p) : "f"(v));
    return p;
}

__device__ __forceinline__ void cp_async16(uint32_t dst, const float* src) {
    asm volatile("cp.async.cg.shared.global [%0], [%1], 16;\n"
                 :: "r"(dst), "l"(src));
}

__device__ __forceinline__ void sts32(uint32_t dst, float v) {
    asm volatile("st.shared.f32 [%0], %1;\n" :: "r"(dst), "f"(v));
}

__global__ __launch_bounds__(256, 5)
void lc2d_kernel(const float* __restrict__ xin,
                 const float* __restrict__ wgt,
                 float* __restrict__ out) {
    __shared__ __align__(16) float sh_w[3 * WBUF];
    __shared__ __align__(16) float sh_x[3 * XBUF];

    const int tid  = threadIdx.x;
    const int xl   = tid & 15;
    const int slot = tid >> 4;
    const int sb   = slot & 3;     // batch group
    const int ob   = slot >> 2;    // out-chan group

    const int y  = blockIdx.y;
    const int x0 = blockIdx.x * TX;
    const int xt = min(TX, OW_ - x0);       // 16 or 14
    const int c0 = blockIdx.z * NC;
    const int sh = 2 * (y & 1);             // uniform 16B-alignment shift

    const uint32_t shw_base = (uint32_t)__cvta_generic_to_shared(sh_w);
    const uint32_t shx_base = (uint32_t)__cvta_generic_to_shared(sh_x);

    // ---- weight staging descriptors (16B chunks), 32-bit offsets ----
    const int rowch  = (xt == TX) ? 37 : 32;    // 16B chunks per o-row
    const int nchunk = CO * rowch;
    const float* wcbase = wgt + (((c0 * OH_ + y) * OW_ + x0) * 9) - sh;

    int      wsoff[3];
    uint32_t wdst[3];
    #pragma unroll
    for (int n = 0; n < 3; ++n) {
        int m = tid + 256 * n;
        bool ok = (m < nchunk);
        int o   = ok ? (m / rowch) : 0;
        int ci4 = ok ? ((m - o * rowch) * 4) : -4;   // ci4<0 encodes "skip"
        wsoff[n] = o * WOSTRIDE + ci4;
        wdst[n]  = (uint32_t)(o * WROW + (ci4 < 0 ? 0 : ci4)) * 4;
    }

    // ---- x staging descriptors (LDG->STS), computed once ----
    const int b_x = tid >> 4;
    const int jx  = tid & 15;
    const float* xsb = xin + ((b_x * CIN + c0) * H_ + y) * W_ + x0;
    int      xsrcoff[4];     // -1 => load 0
    uint32_t xdst[4];        // 0xffffffff => no store
    #pragma unroll
    for (int n = 0; n < 4; ++n) {
        int rem = jx + 16 * n;
        int r  = rem / 18;
        int cc = rem - r * 18;
        bool valid = (rem < 54);
        bool ok = valid && (x0 + cc < W_);
        xsrcoff[n] = ok ? (r * W_ + cc) : -1;
        xdst[n] = valid
            ? (uint32_t)((b_x >> 1) * 120 + r * 40 + cc * 2 + (b_x & 1)) * 4
            : 0xffffffffu;
    }

    float xr[4];
    unsigned long long acc[4][2];
    #pragma unroll
    for (int oo = 0; oo < 4; ++oo) { acc[oo][0] = 0ull; acc[oo][1] = 0ull; }

    auto stage_w = [&](int buf, int ci) {
        uint32_t wb = shw_base + (uint32_t)buf * (WBUF * 4);
        const float* base = wcbase + ci * WCSTRIDE;
        #pragma unroll
        for (int n = 0; n < 3; ++n)
            if (wsoff[n] >= 0 || n < 2)      // n<2 always valid (nchunk>=512)
                if (n < 2 || wsoff[n] >= 0)
                    cp_async16(wb + wdst[n], base + wsoff[n]);
        asm volatile("cp.async.commit_group;\n" ::: "memory");
    };

    auto ldg_x = [&](int ci) {
        const float* base = xsb + ci * XCSTRIDE;
        #pragma unroll
        for (int n = 0; n < 4; ++n)
            xr[n] = (xsrcoff[n] >= 0) ? __ldg(base + xsrcoff[n]) : 0.0f;
    };

    auto sts_x = [&](int buf) {
        uint32_t xb = shx_base + (uint32_t)buf * (XBUF * 4);
        #pragma unroll
        for (int n = 0; n < 4; ++n)
            if (xdst[n] != 0xffffffffu)
                sts32(xb + xdst[n], xr[n]);
    };

    // ---- prologue: w(0), w(1) in flight; x(0) in smem; x(1) in regs ----
    stage_w(0, 0);
    stage_w(1, 1);
    ldg_x(0);
    sts_x(0);
    ldg_x(1);

    int rd = 0;
    #pragma unroll 1
    for (int ci = 0; ci < NC; ++ci) {
        if (ci < NC - 1) {
            asm volatile("cp.async.wait_group 1;\n" ::: "memory");
        } else {
            asm volatile("cp.async.wait_group 0;\n" ::: "memory");
        }
        __syncthreads();   // w(ci) complete; x(ci) STS drained; buf (rd+2)%3 free

        int nxt = rd + 1; if (nxt == 3) nxt = 0;
        if (ci + 1 < NC) sts_x(nxt);             // x(ci+1) regs -> smem
        if (ci + 2 < NC) {
            int st = rd - 1; if (st < 0) st += 3;   // (rd+2)%3
            stage_w(st, ci + 2);
            ldg_x(ci + 2);                       // overwrite xr after STS
        }

        const float* swb = sh_w + rd * WBUF + sh;   // fold alignment shift
        const float* sxb = sh_x + rd * XBUF;

        #pragma unroll
        for (int k = 0; k < 9; ++k) {
            const int i = k / 3;
            const int j = k - i * 3;
            unsigned long long xp0 = *reinterpret_cast<const unsigned long long*>(
                &sxb[(sb * 2)     * 120 + i * 40 + (xl + j) * 2]);
            unsigned long long xp1 = *reinterpret_cast<const unsigned long long*>(
                &sxb[(sb * 2 + 1) * 120 + i * 40 + (xl + j) * 2]);
            #pragma unroll
            for (int oo = 0; oo < 4; ++oo) {
                float wv = swb[(ob * 4 + oo) * WROW + xl * 9 + k];
                unsigned long long wb2 = bcast2(wv);
                ffma2(acc[oo][0], xp0, wb2);
                ffma2(acc[oo][1], xp1, wb2);
            }
        }

        ++rd; if (rd == 3) rd = 0;
    }

    // ---- combine: 4 contributions per output (c quarters) ----
    if (xl < xt) {
        #pragma unroll
        for (int oo = 0; oo < 4; ++oo) {
            const int o = ob * 4 + oo;
            #pragma unroll
            for (int bpl = 0; bpl < 2; ++bpl) {
                float lo, hi;
                asm("mov.b64 {%0, %1}, %2;" : "=f"(lo), "=f"(hi) : "l"(acc[oo][bpl]));
                const int b = sb * 4 + bpl * 2;
                atomicAdd(&out[((b * CO + o)       * OH_ + y) * OW_ + x0 + xl], lo);
                atomicAdd(&out[(((b + 1) * CO + o) * OH_ + y) * OW_ + x0 + xl], hi);
            }
        }
    }
}

extern "C" void kernel_launch(void* const* d_in, const int* in_sizes, int n_in,
                              void* d_out, int out_size) {
    const float* x = (const float*)d_in[0];
    const float* w = (const float*)d_in[1];
    float* out = (float*)d_out;

    cudaMemsetAsync(out, 0, (size_t)out_size * sizeof(float));

    dim3 grid((OW_ + TX - 1) / TX, OH_, 4);   // (4, 62, 4) = 992 blocks
    lc2d_kernel<<<grid, 256>>>(x, w, out);
}

// round 8
// speedup vs baseline: 1.0230x; 1.0230x over previous
#include <cuda_runtime.h>
#include <cuda_bf16.h>
#include <cstdint>

// LocallyConnected2d: out[b,o,y,x] = sum_{c,k} x[b,c,y+i,x+j] * w[o,c,y,x,k]
// B=16, C_IN=16, C_OUT=16, H=W=64, OH=OW=62, K=3x3.
//
// R8 = R7 with alignment-correct vectorized epilogue. Output row offset is
// q*62 + x0 with q parity = y parity, so odd-y rows are 8B- (not 16B-)
// aligned: flush a leading red.add.v2 first, then 16B-aligned red.add.v4.
// Core (R5): 16B cp.async w staging, b-pair FFMA2, triple buffer, c-split 4.

#define B_  16
#define CIN 16
#define CO  16
#define H_  64
#define W_  64
#define OH_ 62
#define OW_ 62
#define TX  16

#define NC  4                       // channels per block (4-way c split)
#define WROW 148                    // weight smem row stride (floats, 16B mult)
#define WBUF (CO * WROW)            // 2368 floats
#define XBUF (8 * 3 * 40)           // 960 floats: [bpair][row][20 cols x 2]
#define TROW 20                     // transpose row stride (floats)

#define WOSTRIDE (CIN * OH_ * OW_ * 9)   // weight float stride per o: 553536
#define WCSTRIDE (OH_ * OW_ * 9)         // weight float stride per c: 34596
#define XCSTRIDE (H_ * W_)               // x float stride per c: 4096

__device__ __forceinline__ void ffma2(unsigned long long& d,
                                      unsigned long long a,
                                      unsigned long long b) {
    asm("fma.rn.f32x2 %0, %1, %2, %0;" : "+l"(d) : "l"(a), "l"(b));
}

__device__ __forceinline__ unsigned long long bcast2(float v) {
    unsigned long long p;
    asm("mov.b64 %0, {%1, %1};" : "=l"(p) : "f"(v));
    return p;
}

__device__ __forceinline__ void cp_async16(uint32_t dst, const float* src) {
    asm volatile("cp.async.cg.shared.global [%0], [%1], 16;\n"
                 :: "r"(dst), "l"(src));
}

__device__ __forceinline__ void cp_async4(uint32_t dst, const float* src, int sz) {
    asm volatile("cp.async.ca.shared.global [%0], [%1], 4, %2;\n"
                 :: "r"(dst), "l"(src), "r"(sz));
}

__device__ __forceinline__ void red_add_v4(float* gptr, float a, float b,
                                           float c, float d) {
    asm volatile("red.global.add.v4.f32 [%0], {%1, %2, %3, %4};\n"
                 :: "l"(gptr), "f"(a), "f"(b), "f"(c), "f"(d) : "memory");
}

__device__ __forceinline__ void red_add_v2(float* gptr, float a, float b) {
    asm volatile("red.global.add.v2.f32 [%0], {%1, %2};\n"
                 :: "l"(gptr), "f"(a), "f"(b) : "memory");
}

__global__ __launch_bounds__(256, 4)
void lc2d_kernel(const float* __restrict__ xin,
                 const float* __restrict__ wgt,
                 float* __restrict__ out) {
    __shared__ __align__(16) float sh_w[3 * WBUF];
    __shared__ __align__(16) float sh_x[3 * XBUF];

    const int tid  = threadIdx.x;
    const int xl   = tid & 15;
    const int slot = tid >> 4;
    const int sb   = slot & 3;     // batch group: b = sb*4 + ...
    const int ob   = slot >> 2;    // out-chan group: o = ob*4 + ...

    const int y  = blockIdx.y;
    const int x0 = blockIdx.x * TX;
    const int xt = min(TX, OW_ - x0);       // 16 or 14
    const int c0 = blockIdx.z * NC;
    const int sh = 2 * (y & 1);             // uniform 16B-alignment shift

    const uint32_t shw_base = (uint32_t)__cvta_generic_to_shared(sh_w);
    const uint32_t shx_base = (uint32_t)__cvta_generic_to_shared(sh_x);

    // ---- weight staging descriptors (16B chunks), computed once ----
    const int rowch  = (xt == TX) ? 37 : 32;    // 16B chunks per o-row
    const int nchunk = CO * rowch;
    const float* wcbase = wgt + (((c0 * OH_ + y) * OW_ + x0) * 9) - sh;

    const float* wsrc[3];
    uint32_t     wdst[3];
    bool         wok[3];
    #pragma unroll
    for (int n = 0; n < 3; ++n) {
        int m = tid + 256 * n;
        wok[n] = (m < nchunk);
        int o   = m / rowch;
        int ci4 = (m - o * rowch) * 4;
        if (o > 15) { o = 15; ci4 = 0; }
        wsrc[n] = wcbase + o * WOSTRIDE + ci4;
        wdst[n] = (uint32_t)(o * WROW + ci4) * 4;
    }

    // ---- x staging descriptors (4B, b-pair interleaved), computed once ----
    const int b_x = tid >> 4;
    const int jx  = tid & 15;
    const float* xsb = xin + ((b_x * CIN + c0) * H_ + y) * W_ + x0;
    int      xsrcoff[4], xsz[4];
    uint32_t xdst[4];
    bool     xvalid[4];
    #pragma unroll
    for (int n = 0; n < 4; ++n) {
        int rem = jx + 16 * n;
        xvalid[n] = (rem < 54);
        int r  = rem / 18;
        int cc = rem - r * 18;
        bool ok = xvalid[n] && (x0 + cc < W_);
        xsrcoff[n] = ok ? (r * W_ + cc) : 0;
        xsz[n]     = ok ? 4 : 0;
        xdst[n] = (uint32_t)((b_x >> 1) * 120 + r * 40 + cc * 2 + (b_x & 1)) * 4;
    }

    unsigned long long acc[4][2];
    #pragma unroll
    for (int oo = 0; oo < 4; ++oo) { acc[oo][0] = 0ull; acc[oo][1] = 0ull; }

    auto stage = [&](int buf, int ci) {
        uint32_t wb = shw_base + (uint32_t)buf * (WBUF * 4);
        #pragma unroll
        for (int n = 0; n < 3; ++n)
            if (wok[n]) cp_async16(wb + wdst[n], wsrc[n] + ci * WCSTRIDE);
        uint32_t xb = shx_base + (uint32_t)buf * (XBUF * 4);
        #pragma unroll
        for (int n = 0; n < 4; ++n)
            if (xvalid[n])
                cp_async4(xb + xdst[n], xsb + ci * XCSTRIDE + xsrcoff[n], xsz[n]);
        asm volatile("cp.async.commit_group;\n" ::: "memory");
    };

    // prologue: two channels in flight
    stage(0, 0);
    stage(1, 1);

    int rd = 0;
    #pragma unroll 1
    for (int ci = 0; ci < NC; ++ci) {
        if (ci < NC - 1) {
            asm volatile("cp.async.wait_group 1;\n" ::: "memory");
        } else {
            asm volatile("cp.async.wait_group 0;\n" ::: "memory");
        }
        __syncthreads();

        if (ci + 2 < NC) {
            int st = rd - 1; if (st < 0) st += 3;   // (rd+2)%3
            stage(st, ci + 2);
        }

        const float* swb = sh_w + rd * WBUF + sh;   // fold alignment shift in
        const float* sxb = sh_x + rd * XBUF;

        #pragma unroll
        for (int k = 0; k < 9; ++k) {
            const int i = k / 3;
            const int j = k - i * 3;
            unsigned long long xp0 = *reinterpret_cast<const unsigned long long*>(
                &sxb[(sb * 2)     * 120 + i * 40 + (xl + j) * 2]);
            unsigned long long xp1 = *reinterpret_cast<const unsigned long long*>(
                &sxb[(sb * 2 + 1) * 120 + i * 40 + (xl + j) * 2]);
            #pragma unroll
            for (int oo = 0; oo < 4; ++oo) {
                float wv = swb[(ob * 4 + oo) * WROW + xl * 9 + k];
                unsigned long long wb2 = bcast2(wv);
                ffma2(acc[oo][0], xp0, wb2);
                ffma2(acc[oo][1], xp1, wb2);
            }
        }

        ++rd; if (rd == 3) rd = 0;
    }

    // ---- epilogue: transpose through smem, flush with aligned red.add ----
    __syncthreads();                       // all compute reads of sh_w done
    float* tr = sh_w;                      // reuse: 256 rows x TROW floats

    #pragma unroll
    for (int oo = 0; oo < 4; ++oo) {
        const int o = ob * 4 + oo;
        #pragma unroll
        for (int bpl = 0; bpl < 2; ++bpl) {
            float lo, hi;
            asm("mov.b64 {%0, %1}, %2;" : "=f"(lo), "=f"(hi) : "l"(acc[oo][bpl]));
            const int b = sb * 4 + bpl * 2;
            tr[(o * 16 + b)     * TROW + xl] = lo;
            tr[(o * 16 + b + 1) * TROW + xl] = hi;
        }
    }
    __syncthreads();

    // thread t owns row t: o = t/16, b = t%16.
    // Row base float-offset ≡ 2*(y&1) (mod 4): odd y needs a leading v2.
    {
        const int o = tid >> 4;
        const int b = tid & 15;
        float* g = out + ((b * CO + o) * OH_ + y) * OW_ + x0;
        const float* r = &tr[tid * TROW];

        int off = 0;
        if (y & 1) {                       // 8B-aligned leading pair
            red_add_v2(g, r[0], r[1]);
            off = 2;
        }
        const int rem   = xt - off;        // 16,14,14,12
        const int quads = rem >> 2;        // 4 or 3
        #pragma unroll 4
        for (int q = 0; q < quads; ++q)
            red_add_v4(g + off + q * 4,
                       r[off + q*4], r[off + q*4 + 1],
                       r[off + q*4 + 2], r[off + q*4 + 3]);
        if (rem & 2) {                     // 8B-aligned tail pair
            const int t = off + quads * 4;
            red_add_v2(g + t, r[t], r[t + 1]);
        }
    }
}

extern "C" void kernel_launch(void* const* d_in, const int* in_sizes, int n_in,
                              void* d_out, int out_size) {
    const float* x = (const float*)d_in[0];
    const float* w = (const float*)d_in[1];
    float* out = (float*)d_out;

    cudaMemsetAsync(out, 0, (size_t)out_size * sizeof(float));

    dim3 grid((OW_ + TX - 1) / TX, OH_, 4);   // (4, 62, 4) = 992 blocks
    lc2d_kernel<<<grid, 256>>>(x, w, out);
}

// round 9
// speedup vs baseline: 1.2081x; 1.1810x over previous
#include <cuda_runtime.h>
#include <cuda_bf16.h>
#include <cstdint>

// LocallyConnected2d: out[b,o,y,x] = sum_{c,k} x[b,c,y+i,x+j] * w[o,c,y,x,k]
// B=16, C_IN=16, C_OUT=16, H=W=64, OH=OW=62, K=3x3.
//
// R9: 128-thread blocks, 8b x 4o x 1xl per thread (32 accs). x staged
// b-quad-interleaved -> LDS.128 per 4 batches; w natural [o][144] smem with
// broadcast scalar LDS; 16 FFMA2 per k (62% payload density, up from 42%).
// 16B cp.async w staging, triple buffer, c-split 4, scalar atomicAdd
// epilogue into memset-0 output (4 commutative contributions/elem).

#define B_  16
#define CIN 16
#define CO  16
#define H_  64
#define W_  64
#define OH_ 62
#define OW_ 62
#define TX  16
#define NT  128

#define NC  4                       // channels per block (4-way c split)
#define WROW 148                    // weight smem row stride (floats, 16B mult)
#define WBUF (CO * WROW)            // 2368 floats
#define XBUF (4 * 3 * 80)           // 960 floats: [bquad][row][col*4 + bl]
#define BQS  240                    // bquad stride (floats)

#define WOSTRIDE (CIN * OH_ * OW_ * 9)   // weight float stride per o
#define WCSTRIDE (OH_ * OW_ * 9)         // weight float stride per c
#define XCSTRIDE (H_ * W_)               // x float stride per c

__device__ __forceinline__ void ffma2(unsigned long long& d,
                                      unsigned long long a,
                                      unsigned long long b) {
    asm("fma.rn.f32x2 %0, %1, %2, %0;" : "+l"(d) : "l"(a), "l"(b));
}

__device__ __forceinline__ unsigned long long bcast2(float v) {
    unsigned long long p;
    asm("mov.b64 %0, {%1, %1};" : "=l"(p) : "f"(v));
    return p;
}

__device__ __forceinline__ void cp_async16(uint32_t dst, const float* src) {
    asm volatile("cp.async.cg.shared.global [%0], [%1], 16;\n"
                 :: "r"(dst), "l"(src));
}

__device__ __forceinline__ void cp_async4(uint32_t dst, const float* src, int sz) {
    asm volatile("cp.async.ca.shared.global [%0], [%1], 4, %2;\n"
                 :: "r"(dst), "l"(src), "r"(sz));
}

__global__ __launch_bounds__(NT, 5)
void lc2d_kernel(const float* __restrict__ xin,
                 const float* __restrict__ wgt,
                 float* __restrict__ out) {
    __shared__ __align__(16) float sh_w[3 * WBUF];
    __shared__ __align__(16) float sh_x[3 * XBUF];

    const int tid = threadIdx.x;
    const int xl  = tid & 15;
    const int grp = tid >> 4;      // 0..7
    const int bh  = grp & 1;       // b half: b in [bh*8, bh*8+8)
    const int ob  = grp >> 1;      // o group: o in [ob*4, ob*4+4)

    const int y  = blockIdx.y;
    const int x0 = blockIdx.x * TX;
    const int xt = min(TX, OW_ - x0);       // 16 or 14
    const int c0 = blockIdx.z * NC;
    const int sh = 2 * (y & 1);             // uniform 16B-alignment shift

    const uint32_t shw_base = (uint32_t)__cvta_generic_to_shared(sh_w);
    const uint32_t shx_base = (uint32_t)__cvta_generic_to_shared(sh_x);

    // ---- weight staging descriptors (16B chunks, 5 slots) ----
    const int rowch  = (xt == TX) ? 37 : 32;
    const int nchunk = CO * rowch;          // 592 or 512
    const float* wcbase = wgt + (((c0 * OH_ + y) * OW_ + x0) * 9) - sh;

    int      wsoff[5];
    uint32_t wdst[5];
    bool     wok[5];
    #pragma unroll
    for (int n = 0; n < 5; ++n) {
        int m = tid + NT * n;
        wok[n] = (m < nchunk);
        int o   = m / rowch;
        int ci4 = (m - o * rowch) * 4;
        if (o > 15) { o = 15; ci4 = 0; }
        wsoff[n] = o * WOSTRIDE + ci4;
        wdst[n]  = (uint32_t)(o * WROW + ci4) * 4;
    }

    // ---- x staging descriptors (4B, b-quad interleaved, 7 slots) ----
    // element m -> b = m/54, rem = m%54, r = rem/18, cc = rem%18
    int      xsrcoff[7], xsz[7];
    uint32_t xdst[7];
    bool     xvalid[7];
    #pragma unroll
    for (int n = 0; n < 7; ++n) {
        int m = tid + NT * n;
        xvalid[n] = (m < B_ * 54);
        int b   = m / 54;
        int rem = m - b * 54;
        int r   = rem / 18;
        int cc  = rem - r * 18;
        if (!xvalid[n]) { b = 0; r = 0; cc = 0; }
        bool ok = xvalid[n] && (x0 + cc < W_);
        xsrcoff[n] = (b * CIN) * XCSTRIDE + r * W_ + cc;   // + c*XCSTRIDE later
        xsz[n]     = ok ? 4 : 0;
        xdst[n] = (uint32_t)((b >> 2) * BQS + r * 80 + cc * 4 + (b & 3)) * 4;
    }
    const float* xbase = xin + (c0 * H_ + y) * W_ + x0;

    unsigned long long acc[4][2][2];    // [oo][q][pair] : b = (bh*2+q)*4 + 2*pair
    #pragma unroll
    for (int oo = 0; oo < 4; ++oo)
        #pragma unroll
        for (int q = 0; q < 2; ++q) { acc[oo][q][0] = 0ull; acc[oo][q][1] = 0ull; }

    auto stage = [&](int buf, int ci) {
        uint32_t wb = shw_base + (uint32_t)buf * (WBUF * 4);
        const float* wc = wcbase + ci * WCSTRIDE;
        #pragma unroll
        for (int n = 0; n < 5; ++n)
            if (wok[n]) cp_async16(wb + wdst[n], wc + wsoff[n]);
        uint32_t xb = shx_base + (uint32_t)buf * (XBUF * 4);
        const float* xc = xbase + ci * XCSTRIDE;
        #pragma unroll
        for (int n = 0; n < 7; ++n)
            if (xvalid[n])
                cp_async4(xb + xdst[n], xc + xsrcoff[n], xsz[n]);
        asm volatile("cp.async.commit_group;\n" ::: "memory");
    };

    // prologue: two channels in flight
    stage(0, 0);
    stage(1, 1);

    int rd = 0;
    #pragma unroll 1
    for (int ci = 0; ci < NC; ++ci) {
        if (ci < NC - 1) {
            asm volatile("cp.async.wait_group 1;\n" ::: "memory");
        } else {
            asm volatile("cp.async.wait_group 0;\n" ::: "memory");
        }
        __syncthreads();

        if (ci + 2 < NC) {
            int st = rd - 1; if (st < 0) st += 3;   // (rd+2)%3
            stage(st, ci + 2);
        }

        const float* swb = sh_w + rd * WBUF + sh;
        const float* sxb = sh_x + rd * XBUF + bh * (2 * BQS);

        #pragma unroll
        for (int k = 0; k < 9; ++k) {
            const int i = k / 3;
            const int j = k - i * 3;
            // two b-quads via LDS.128 each
            const float* xp = &sxb[i * 80 + (xl + j) * 4];
            ulonglong2 xq0 = *reinterpret_cast<const ulonglong2*>(xp);
            ulonglong2 xq1 = *reinterpret_cast<const ulonglong2*>(xp + BQS);
            #pragma unroll
            for (int oo = 0; oo < 4; ++oo) {
                float wv = swb[(ob * 4 + oo) * WROW + xl * 9 + k];
                unsigned long long wb2 = bcast2(wv);
                ffma2(acc[oo][0][0], xq0.x, wb2);
                ffma2(acc[oo][0][1], xq0.y, wb2);
                ffma2(acc[oo][1][0], xq1.x, wb2);
                ffma2(acc[oo][1][1], xq1.y, wb2);
            }
        }

        ++rd; if (rd == 3) rd = 0;
    }

    // ---- epilogue: scalar atomics (R5-proven), 4 contributions/elem ----
    if (xl < xt) {
        #pragma unroll
        for (int oo = 0; oo < 4; ++oo) {
            const int o = ob * 4 + oo;
            #pragma unroll
            for (int q = 0; q < 2; ++q) {
                const int bq = (bh * 2 + q) * 4;
                #pragma unroll
                for (int p = 0; p < 2; ++p) {
                    float lo, hi;
                    asm("mov.b64 {%0, %1}, %2;"
                        : "=f"(lo), "=f"(hi) : "l"(acc[oo][q][p]));
                    const int b = bq + 2 * p;
                    atomicAdd(&out[((b * CO + o)       * OH_ + y) * OW_ + x0 + xl], lo);
                    atomicAdd(&out[(((b + 1) * CO + o) * OH_ + y) * OW_ + x0 + xl], hi);
                }
            }
        }
    }
}

extern "C" void kernel_launch(void* const* d_in, const int* in_sizes, int n_in,
                              void* d_out, int out_size) {
    const float* x = (const float*)d_in[0];
    const float* w = (const float*)d_in[1];
    float* out = (float*)d_out;

    cudaMemsetAsync(out, 0, (size_t)out_size * sizeof(float));

    dim3 grid((OW_ + TX - 1) / TX, OH_, 4);   // (4, 62, 4) = 992 blocks
    lc2d_kernel<<<grid, NT>>>(x, w, out);
}